// round 10
// baseline (speedup 1.0000x reference)
#include <cuda_runtime.h>
#include <cuda_bf16.h>

// SGConv: out = (D^-1/2 A D^-1/2)^2 * feat @ W + b
// N=100000 nodes, 64 features, E=1000000 edges.
//
// Memory-guard constraints (R1/R3): big __device__ segments trigger a fixed
// 128MiB driver arena inside the checkpoint window; pre-main CUDA calls break
// harness handles (R2). => globals ~5.6MB; h1 lives in d_out; h2 lives in
// shared memory of the persistent fused kernel.
//
// R10 vs R9 (219.1us): (1) CSR build collapsed into ONE persistent kernel
// with internal grid barriers (was 6 launches: zero/hist/scan1/scan2/scan3/
// fill) -> kills 5 launch overheads + drain gaps. (2) hop1 uses the proven
// half-warp float4 gather (2 rows/warp). Launch order init,build,hop1,fused
// also puts k_fused at captured ncu launch index 3 for next-round profiling.
// k_fused itself unchanged from R9 (512 thr, 128-reg cap, no spills).

#define MAXN 100000
#define MAXE 1000000
#define F 64
#define ROWS_PB_CAP 760
#define H2S 68          // h2 row stride in floats (mult of 4 -> aligned float4)
#define SPIN_BOUND (160LL << 20)

__device__ int   g_deg[MAXN];
__device__ int   g_rowptr[MAXN + 1];
__device__ int   g_cur[MAXN];
__device__ int   g_chunksum[256];
__device__ float g_norm[MAXN];
__device__ int   g_csr_src[MAXE];
__device__ int   g_bar_build;
__device__ int   g_bar_fused;

// ---------------------------------------------------------------- init (resets build barrier)
__global__ void k_init() { g_bar_build = 0; }

// ---------------------------------------------------------------- grid barrier helper
// Monotone counter; phase p waits for count >= p*nblocks. Bounded spin.
__device__ __forceinline__ void grid_bar(int nblocks, int phase) {
    __syncthreads();
    __threadfence();
    if (threadIdx.x == 0) {
        atomicAdd(&g_bar_build, 1);
        long long guard = 0;
        while (atomicAdd(&g_bar_build, 0) < phase * nblocks &&
               guard < SPIN_BOUND) { __nanosleep(32); guard++; }
    }
    __syncthreads();
}

// ---------------------------------------------------------------- persistent CSR build
// nblocks <= #SMs, 1024 threads, tiny smem/regs -> all blocks co-resident.
// stages: zero | hist | chunk-sums | scan(+norm,+rowptr) | fill
__global__ void __launch_bounds__(1024)
k_build(const int* __restrict__ src, const int* __restrict__ dst,
        int N, int E, int nblocks) {
    __shared__ int sh[1024];
    __shared__ int shc[256];
    __shared__ int s_off;

    int t   = threadIdx.x;
    int b   = blockIdx.x;
    int gid = b * 1024 + t;
    int gsz = nblocks * 1024;
    int C   = (N + nblocks - 1) / nblocks;     // chunk size per block (<=1024)
    int lo  = b * C;
    int hi  = min(N, lo + C);

    // ---- stage 0: zero
    for (int i = gid; i < N; i += gsz) { g_deg[i] = 0; g_cur[i] = 0; }
    if (gid == 0) g_bar_fused = 0;
    grid_bar(nblocks, 1);

    // ---- stage 1: histogram
    for (int e = gid; e < E; e += gsz) atomicAdd(&g_deg[dst[e]], 1);
    grid_bar(nblocks, 2);

    // ---- stage 2: per-chunk sums
    {
        int s = 0;
        for (int i = lo + t; i < hi; i += 1024) s += g_deg[i];
        sh[t] = s;
        __syncthreads();
        for (int off = 512; off > 0; off >>= 1) {
            if (t < off) sh[t] += sh[t + off];
            __syncthreads();
        }
        if (t == 0) g_chunksum[b] = sh[0];
    }
    grid_bar(nblocks, 3);

    // ---- stage 3: every block scans the chunk sums; then scans own chunk
    {
        int v = (t < nblocks) ? g_chunksum[t] : 0;
        if (t < 256) shc[t] = v;
        __syncthreads();
        for (int off = 1; off < 256; off <<= 1) {
            int x = (t >= off && t < 256) ? shc[t - off] : 0;
            __syncthreads();
            if (t < 256) shc[t] += x;
            __syncthreads();
        }
        if (t == 0) s_off = (b == 0) ? 0 : shc[b - 1];   // exclusive offset
        __syncthreads();

        // own chunk scan (C <= 1024, single Hillis-Steele pass)
        int i = lo + t;
        int v2 = (t < C && i < hi) ? g_deg[i] : 0;
        if (t < C && i < hi) g_norm[i] = rsqrtf(fmaxf((float)v2, 1.0f));
        sh[t] = v2;
        __syncthreads();
        for (int off = 1; off < 1024; off <<= 1) {
            int x = (t >= off) ? sh[t - off] : 0;
            __syncthreads();
            sh[t] += x;
            __syncthreads();
        }
        if (t < C && i < hi) g_rowptr[i] = s_off + sh[t] - v2;  // exclusive
        if (b == nblocks - 1 && t == 0) g_rowptr[N] = E;
    }
    grid_bar(nblocks, 4);

    // ---- stage 4: CSR fill
    for (int e = gid; e < E; e += gsz) {
        int d = dst[e];
        int p = g_rowptr[d] + atomicAdd(&g_cur[d], 1);
        g_csr_src[p] = src[e];
    }
}

// ---------------------------------------------------------------- hop1
// half-warp per dst row; 16 lanes x float4 = 256B row. 2 rows/warp.
__global__ void k_hop1(const float* __restrict__ x, float* __restrict__ y, int N) {
    int idx = blockIdx.x * blockDim.x + threadIdx.x;
    int hw  = idx >> 4;          // half-warp id = row
    int lh  = idx & 15;
    if (hw >= N) return;
    int beg = g_rowptr[hw];
    int end = g_rowptr[hw + 1];
    float nd = g_norm[hw];
    float4 acc = make_float4(0.f, 0.f, 0.f, 0.f);
    const float4* xf = (const float4*)x;
    for (int j = beg; j < end; j++) {
        int   s = __ldg(&g_csr_src[j]);
        float w = __ldg(&g_norm[s]);
        float4 v = xf[s * 16 + lh];
        acc.x += w * v.x; acc.y += w * v.y;
        acc.z += w * v.z; acc.w += w * v.w;
    }
    acc.x *= nd; acc.y *= nd; acc.z *= nd; acc.w *= nd;
    ((float4*)y)[hw * 16 + lh] = acc;
}

// ---------------------------------------------------------------- fused hop2 + GEMM
// Unchanged from R9 (proven): 512 threads, half-warp float4 gather into smem,
// grid barrier, 4x4-tile GEMM. x and out ALIAS (= d_out).
__global__ void __launch_bounds__(512, 1)
k_fused(const float* x, float* out, const float* __restrict__ Wm,
        const float* __restrict__ bias, int N, int rows_pb, int nblocks) {
    extern __shared__ float sm[];
    float* h2 = sm;                        // rows_pb * H2S
    float* Ws = sm + rows_pb * H2S;        // 64*64

    int tid  = threadIdx.x;
    int wid  = tid >> 5;
    int lane = tid & 31;
    int half = lane >> 4;
    int lh   = lane & 15;
    int row0 = blockIdx.x * rows_pb;

    for (int i = tid; i < F * F; i += blockDim.x) Ws[i] = Wm[i];

    // ---- phase 1: half-warp gathers one row; float4 per lane
    const float4* xf = (const float4*)x;
    for (int lr = (wid << 1) | half; lr < rows_pb; lr += 32) {
        int r = row0 + lr;
        float4 acc = make_float4(0.f, 0.f, 0.f, 0.f);
        if (r < N) {
            int beg = g_rowptr[r];
            int end = g_rowptr[r + 1];
            float nd = g_norm[r];
            for (int j = beg; j < end; j++) {
                int   s = __ldg(&g_csr_src[j]);
                float w = __ldg(&g_norm[s]);
                float4 v = xf[s * 16 + lh];
                acc.x += w * v.x; acc.y += w * v.y;
                acc.z += w * v.z; acc.w += w * v.w;
            }
            acc.x *= nd; acc.y *= nd; acc.z *= nd; acc.w *= nd;
        }
        *(float4*)&h2[lr * H2S + 4 * lh] = acc;
    }

    // ---- software grid barrier (all blocks resident; bounded spin)
    __syncthreads();
    __threadfence();
    if (tid == 0) {
        atomicAdd(&g_bar_fused, 1);
        long long guard = 0;
        while (*(volatile int*)&g_bar_fused < nblocks && guard < SPIN_BOUND) {
            __nanosleep(64);
            guard++;
        }
    }
    __syncthreads();
    __threadfence();

    // ---- phase 2: out rows = h2 @ W + b, 128-row tiles, 4x4 per thread
    int tx = tid & 15;
    int ty = tid >> 4;
    int c0 = tx * 4;
    float4 bv = *(const float4*)&bias[c0];

    for (int t0 = 0; t0 < rows_pb; t0 += 128) {
        float acc[4][4];
        #pragma unroll
        for (int i = 0; i < 4; i++) {
            acc[i][0] = bv.x; acc[i][1] = bv.y; acc[i][2] = bv.z; acc[i][3] = bv.w;
        }
        int rbase = t0 + ty * 4;
        int rr[4];
        #pragma unroll
        for (int i = 0; i < 4; i++) {
            int r = rbase + i;
            rr[i] = (r < rows_pb) ? r : (rows_pb - 1);
        }
        #pragma unroll
        for (int k = 0; k < F; k++) {
            float4 wv = *(const float4*)&Ws[k * F + c0];
            #pragma unroll
            for (int i = 0; i < 4; i++) {
                float yv = h2[rr[i] * H2S + k];
                acc[i][0] += yv * wv.x;
                acc[i][1] += yv * wv.y;
                acc[i][2] += yv * wv.z;
                acc[i][3] += yv * wv.w;
            }
        }
        #pragma unroll
        for (int i = 0; i < 4; i++) {
            int lr = rbase + i;
            int g  = row0 + lr;
            if (lr < rows_pb && g < N) {
                float4 v = make_float4(acc[i][0], acc[i][1], acc[i][2], acc[i][3]);
                *(float4*)(out + g * F + c0) = v;
            }
        }
    }
}

// ---------------------------------------------------------------- launch
extern "C" void kernel_launch(void* const* d_in, const int* in_sizes, int n_in,
                              void* d_out, int out_size) {
    const float* feat = (const float*)d_in[0];
    const int*   src  = (const int*)d_in[1];
    const int*   dst  = (const int*)d_in[2];
    const float* Wm   = (const float*)d_in[3];
    const float* bias = (const float*)d_in[4];
    float* out = (float*)d_out;

    int N = in_sizes[0] / F;   // 100000
    int E = in_sizes[1];       // 1000000

    int dev = 0;
    cudaGetDevice(&dev);
    int smcount = 0;
    cudaDeviceGetAttribute(&smcount, cudaDevAttrMultiProcessorCount, dev);
    if (smcount <= 0) smcount = 148;

    // build kernel: need C = ceil(N/nb) <= 1024 -> nb >= 98; smcount is 148.
    int nb_build = smcount;
    if (nb_build > 256) nb_build = 256;            // chunksum array bound

    int rows_pb = (N + smcount - 1) / smcount;
    if (rows_pb > ROWS_PB_CAP) rows_pb = ROWS_PB_CAP;
    int nblocks = (N + rows_pb - 1) / rows_pb;
    if (nblocks > smcount) nblocks = smcount;
    rows_pb = (N + nblocks - 1) / nblocks;
    size_t smem = (size_t)(rows_pb * H2S + F * F) * sizeof(float);
    cudaFuncSetAttribute(k_fused, cudaFuncAttributeMaxDynamicSharedMemorySize,
                         (int)smem);

    int nb_hop = (N * 16 + 255) / 256;             // half-warp per row

    k_init<<<1, 1>>>();
    k_build<<<nb_build, 1024>>>(src, dst, N, E, nb_build);
    k_hop1<<<nb_hop, 256>>>(feat, out, N);
    k_fused<<<nblocks, 512, smem>>>(out, out, Wm, bias, N, rows_pb, nblocks);
}